// round 1
// baseline (speedup 1.0000x reference)
#include <cuda_runtime.h>
#include <cuda_bf16.h>

// f_z[b,i] = z[b,i] + sum_{j<i} h[b, i*(i-1)/2 + j] * z[b,j]
// h: packed strictly-lower-triangular, row-major (row i has i entries).
// Pure HBM-streaming problem: h (134 MB) read once. One warp per (b, i) row,
// coalesced 128B warp-steps over h, z served from shared memory.

#define DIM 512
#define HLEN ((DIM * (DIM - 1)) / 2)   // 130816
#define ROWS_PER_CTA 8
#define THREADS 256
#define ROW_GROUPS (DIM / ROWS_PER_CTA) // 64

__global__ __launch_bounds__(THREADS) void LinearMap_kernel(
    const float* __restrict__ z,
    const float* __restrict__ h,
    float* __restrict__ out)
{
    __shared__ float zs[DIM];

    const int b    = blockIdx.x >> 6;          // / ROW_GROUPS
    const int rg   = blockIdx.x & (ROW_GROUPS - 1);
    const int tid  = threadIdx.x;
    const int warp = tid >> 5;
    const int lane = tid & 31;

    // Stage z[b] into shared memory (2 KB), coalesced.
    const float* zb = z + (size_t)b * DIM;
    #pragma unroll
    for (int j = tid; j < DIM; j += THREADS) zs[j] = zb[j];
    __syncthreads();

    const int i = rg * ROWS_PER_CTA + warp;    // output row, 0..511
    const float* __restrict__ hrow =
        h + (size_t)b * HLEN + ((size_t)i * (size_t)(i - 1)) / 2;

    float s = 0.0f;
    int j = lane;
    // Main loop: 4 coalesced 128B warp-steps per iteration (MLP=4/lane).
    for (; j + 96 < i; j += 128) {
        float h0 = __ldcs(hrow + j);
        float h1 = __ldcs(hrow + j + 32);
        float h2 = __ldcs(hrow + j + 64);
        float h3 = __ldcs(hrow + j + 96);
        s = fmaf(h0, zs[j],      s);
        s = fmaf(h1, zs[j + 32], s);
        s = fmaf(h2, zs[j + 64], s);
        s = fmaf(h3, zs[j + 96], s);
    }
    // Remainder.
    for (; j < i; j += 32) {
        s = fmaf(__ldcs(hrow + j), zs[j], s);
    }

    // Warp reduction.
    #pragma unroll
    for (int off = 16; off; off >>= 1)
        s += __shfl_xor_sync(0xffffffffu, s, off);

    if (lane == 0)
        out[(size_t)b * DIM + i] = zs[i] + s;
}

// Zero the logdet tail (and anything past f_z) — d_out is poisoned to 0xAA.
__global__ void LinearMap_tail_kernel(float* __restrict__ out, int start, int total)
{
    int k = start + blockIdx.x * blockDim.x + threadIdx.x;
    if (k < total) out[k] = 0.0f;
}

extern "C" void kernel_launch(void* const* d_in, const int* in_sizes, int n_in,
                              void* d_out, int out_size)
{
    const float* z = (const float*)d_in[0];   // [batch, 512]
    const float* h = (const float*)d_in[1];   // [batch, 130816]
    float* out = (float*)d_out;

    const int batch = in_sizes[0] / DIM;      // 256

    dim3 grid(batch * ROW_GROUPS);            // 16384 CTAs, 8 rows each
    LinearMap_kernel<<<grid, THREADS>>>(z, h, out);

    const int nfz = batch * DIM;
    if (out_size > nfz) {
        int tail = out_size - nfz;            // 1 (logdet)
        int tb = 128;
        LinearMap_tail_kernel<<<(tail + tb - 1) / tb, tb>>>(out, nfz, out_size);
    }
}

// round 3
// speedup vs baseline: 1.0546x; 1.0546x over previous
#include <cuda_runtime.h>
#include <cuda_bf16.h>
#include <cstdint>

// f_z[b,i] = z[b,i] + sum_{j<i} h[b, i*(i-1)/2 + j] * z[b,j]
// h packed strictly-lower-triangular row-major. HBM-streaming bound.
//
// One warp handles the ROW PAIR (i, 511-i): combined length is always 511,
// so every warp / CTA does identical work (perfect wave balance).
// h rows read with aligned float4 (LDG.128) after a <=3-elem scalar
// alignment prologue; z served from a per-CTA shared copy.

#define DIM 512
#define HLEN ((DIM * (DIM - 1)) / 2)   // 130816 (multiple of 4)
#define THREADS 256
#define WARPS_PER_CTA 8
#define PAIRS (DIM / 2)                 // 256 pairs
#define CTAS_PER_BATCH (PAIRS / WARPS_PER_CTA) // 32

// hoff = packed offset of the row (known % 4 via arithmetic, no ptr cast)
__device__ __forceinline__ float row_dot(const float* __restrict__ hb,
                                         unsigned hoff,
                                         const float* __restrict__ zs,
                                         int len, int lane)
{
    const float* hrow = hb + hoff;
    float s = 0.0f;
    int mis = (int)(hoff & 3u);
    int p = (4 - mis) & 3;
    if (p > len) p = len;
    if (lane < p) s = hrow[lane] * zs[lane];

    int n  = len - p;
    int nv = n >> 2;                       // aligned float4 count
    const float4* h4 = (const float4*)(hrow + p);

    #pragma unroll 2
    for (int v = lane; v < nv; v += 32) {
        float4 hv = __ldcs(h4 + v);
        int j = p + (v << 2);
        s = fmaf(hv.x, zs[j],     s);
        s = fmaf(hv.y, zs[j + 1], s);
        s = fmaf(hv.z, zs[j + 2], s);
        s = fmaf(hv.w, zs[j + 3], s);
    }
    int rbase = p + (nv << 2);
    int rem = n & 3;
    if (lane < rem)
        s = fmaf(__ldcs(hrow + rbase + lane), zs[rbase + lane], s);

    #pragma unroll
    for (int off = 16; off; off >>= 1)
        s += __shfl_xor_sync(0xffffffffu, s, off);
    return s;   // valid in all lanes
}

__global__ __launch_bounds__(THREADS) void LinearMap_kernel(
    const float* __restrict__ z,
    const float* __restrict__ h,
    float* __restrict__ out,
    int out_size)
{
    __shared__ float zs[DIM];

    const int b    = blockIdx.x / CTAS_PER_BATCH;
    const int pg   = blockIdx.x % CTAS_PER_BATCH;
    const int tid  = threadIdx.x;
    const int warp = tid >> 5;
    const int lane = tid & 31;

    const float* zb = z + (size_t)b * DIM;
    #pragma unroll
    for (int j = tid; j < DIM; j += THREADS) zs[j] = zb[j];
    __syncthreads();

    const float* hb = h + (size_t)b * HLEN;
    const int ia = pg * WARPS_PER_CTA + warp;  // short row, 0..255
    const int ib = DIM - 1 - ia;               // long row, 256..511

    float sa = row_dot(hb, (unsigned)(ia * (ia - 1) / 2), zs, ia, lane);
    float sb = row_dot(hb, (unsigned)(ib * (ib - 1) / 2), zs, ib, lane);

    if (lane == 0) {
        float* ob = out + (size_t)b * DIM;
        ob[ia] = zs[ia] + sa;
        ob[ib] = zs[ib] + sb;
    }

    // Fold the logdet / tail zeroing into this kernel (d_out is poisoned).
    if (blockIdx.x == 0) {
        const int nfz = (int)(gridDim.x / CTAS_PER_BATCH) * DIM;
        for (int k = nfz + tid; k < out_size; k += THREADS) out[k] = 0.0f;
    }
}

extern "C" void kernel_launch(void* const* d_in, const int* in_sizes, int n_in,
                              void* d_out, int out_size)
{
    const float* z = (const float*)d_in[0];   // [batch, 512]
    const float* h = (const float*)d_in[1];   // [batch, 130816]
    float* out = (float*)d_out;

    const int batch = in_sizes[0] / DIM;      // 256

    dim3 grid(batch * CTAS_PER_BATCH);        // 8192 CTAs, all identical work
    LinearMap_kernel<<<grid, THREADS>>>(z, h, out, out_size);
}